// round 1
// baseline (speedup 1.0000x reference)
#include <cuda_runtime.h>

#define BB 512
#define SS 4096
#define DD 128
#define KK 409
#define VV 6

// Tables computed by k_tables, consumed by k_main (kernel-boundary ordering
// on the capture stream guarantees visibility).
__device__ float g_score[VV];
__device__ float g_att[VV * DD];

// ---------------------------------------------------------------------------
// Kernel 1: per-class tables. 6 blocks (one per vocab id), 128 threads.
//   score[v] = sigmoid(MLP_importance(emb[v]))
//   att[v]   = MLP_attention(emb[v])
// ---------------------------------------------------------------------------
__global__ void k_tables(const float* __restrict__ emb,
                         const float* __restrict__ W1, const float* __restrict__ b1,
                         const float* __restrict__ W2, const float* __restrict__ b2,
                         const float* __restrict__ W3, const float* __restrict__ b3,
                         const float* __restrict__ A1, const float* __restrict__ a1,
                         const float* __restrict__ A2, const float* __restrict__ a2) {
    const int v = blockIdx.x;
    const int t = threadIdx.x;

    __shared__ float e[DD];
    __shared__ float h1[64];
    __shared__ float h2[32];
    __shared__ float g[64];

    e[t] = emb[v * DD + t];
    __syncthreads();

    if (t < 64) {
        // h1[t] = relu(e @ W1[:,t] + b1[t])
        float s0 = 0.f, s1 = 0.f, s2 = 0.f, s3 = 0.f;
        #pragma unroll
        for (int i = 0; i < DD; i += 4) {
            s0 = fmaf(e[i + 0], W1[(i + 0) * 64 + t], s0);
            s1 = fmaf(e[i + 1], W1[(i + 1) * 64 + t], s1);
            s2 = fmaf(e[i + 2], W1[(i + 2) * 64 + t], s2);
            s3 = fmaf(e[i + 3], W1[(i + 3) * 64 + t], s3);
        }
        h1[t] = fmaxf((s0 + s1) + (s2 + s3) + b1[t], 0.0f);
    } else {
        // g[j] = relu(e @ A1[:,j] + a1[j])
        const int j = t - 64;
        float s0 = 0.f, s1 = 0.f, s2 = 0.f, s3 = 0.f;
        #pragma unroll
        for (int i = 0; i < DD; i += 4) {
            s0 = fmaf(e[i + 0], A1[(i + 0) * 64 + j], s0);
            s1 = fmaf(e[i + 1], A1[(i + 1) * 64 + j], s1);
            s2 = fmaf(e[i + 2], A1[(i + 2) * 64 + j], s2);
            s3 = fmaf(e[i + 3], A1[(i + 3) * 64 + j], s3);
        }
        g[j] = fmaxf((s0 + s1) + (s2 + s3) + a1[j], 0.0f);
    }
    __syncthreads();

    // att[v][t] = g @ A2[:,t] + a2[t]
    {
        float s0 = 0.f, s1 = 0.f, s2 = 0.f, s3 = 0.f;
        #pragma unroll
        for (int j = 0; j < 64; j += 4) {
            s0 = fmaf(g[j + 0], A2[(j + 0) * DD + t], s0);
            s1 = fmaf(g[j + 1], A2[(j + 1) * DD + t], s1);
            s2 = fmaf(g[j + 2], A2[(j + 2) * DD + t], s2);
            s3 = fmaf(g[j + 3], A2[(j + 3) * DD + t], s3);
        }
        g_att[v * DD + t] = (s0 + s1) + (s2 + s3) + a2[t];
    }

    if (t < 32) {
        // h2[t] = relu(h1 @ W2[:,t] + b2[t])
        float s0 = 0.f, s1 = 0.f;
        #pragma unroll
        for (int i = 0; i < 64; i += 2) {
            s0 = fmaf(h1[i + 0], W2[(i + 0) * 32 + t], s0);
            s1 = fmaf(h1[i + 1], W2[(i + 1) * 32 + t], s1);
        }
        h2[t] = fmaxf(s0 + s1 + b2[t], 0.0f);
    }
    __syncthreads();

    if (t == 0) {
        float s = b3[0];
        #pragma unroll
        for (int i = 0; i < 32; i++) s = fmaf(h2[i], W3[i], s);
        g_score[v] = 1.0f / (1.0f + expf(-s));
    }
}

// ---------------------------------------------------------------------------
// Kernel 2: one block per batch row, 256 threads, 16 tokens/thread.
//   - write final_scores via 6-entry LUT (float4 stores)
//   - stable top-k via class histogram + chunk prefix scan (lax.top_k tiebreak)
//   - pooled = sum_v selcnt[v]*att[v] / k ; classifier -> pred
// ---------------------------------------------------------------------------
__global__ void __launch_bounds__(256, 4)
k_main(const int* __restrict__ x,
       const float* __restrict__ C1, const float* __restrict__ c1,
       const float* __restrict__ C2, const float* __restrict__ c2,
       float* __restrict__ out) {
    const int row = blockIdx.x;
    const int tid = threadIdx.x;

    __shared__ float sc[VV];
    __shared__ float att_s[VV * DD];
    __shared__ int   pref[VV][256];   // counts, then exclusive chunk prefixes
    __shared__ int   total_s[VV];
    __shared__ int   base_s[VV];
    __shared__ unsigned eqm[VV];
    __shared__ int   selcnt[VV];
    __shared__ float pooled[DD];
    __shared__ float hbuf[64];

    if (tid < VV) { sc[tid] = g_score[tid]; selcnt[tid] = 0; }
    for (int i = tid; i < VV * DD; i += 256) att_s[i] = g_att[i];
    __syncthreads();

    float* __restrict__ pred_out = out;
    float* __restrict__ top_out  = out + BB;
    float* __restrict__ fs_out   = out + BB + (size_t)BB * KK;

    // ---- Pass A: load 16 tokens/thread, write scores, local histogram ----
    int tok[16];
    {
        const int4* xp = reinterpret_cast<const int4*>(x + (size_t)row * SS) + tid * 4;
        int4 p0 = xp[0], p1 = xp[1], p2 = xp[2], p3 = xp[3];
        tok[0]  = p0.x; tok[1]  = p0.y; tok[2]  = p0.z; tok[3]  = p0.w;
        tok[4]  = p1.x; tok[5]  = p1.y; tok[6]  = p1.z; tok[7]  = p1.w;
        tok[8]  = p2.x; tok[9]  = p2.y; tok[10] = p2.z; tok[11] = p2.w;
        tok[12] = p3.x; tok[13] = p3.y; tok[14] = p3.z; tok[15] = p3.w;

        float4* fo = reinterpret_cast<float4*>(fs_out + (size_t)row * SS) + tid * 4;
        #pragma unroll
        for (int q = 0; q < 4; q++) {
            float4 f;
            f.x = sc[tok[q * 4 + 0]];
            f.y = sc[tok[q * 4 + 1]];
            f.z = sc[tok[q * 4 + 2]];
            f.w = sc[tok[q * 4 + 3]];
            fo[q] = f;
        }
    }
    // histogram with static indexing (stays in registers)
    #pragma unroll
    for (int u = 0; u < VV; u++) {
        int c = 0;
        #pragma unroll
        for (int l = 0; l < 16; l++) c += (tok[l] == u);
        pref[u][tid] = c;
    }
    __syncthreads();

    // ---- Pass B: per-class exclusive prefix over the 256 chunks ----
    {
        const int w = tid >> 5, lane = tid & 31;
        if (w < VV) {
            int carry = 0;
            #pragma unroll
            for (int gseg = 0; gseg < 8; gseg++) {
                int idx = gseg * 32 + lane;
                int v0 = pref[w][idx];
                int incl = v0;
                #pragma unroll
                for (int off = 1; off < 32; off <<= 1) {
                    int n = __shfl_up_sync(0xFFFFFFFFu, incl, off);
                    if (lane >= off) incl += n;
                }
                pref[w][idx] = carry + incl - v0;     // exclusive
                carry += __shfl_sync(0xFFFFFFFFu, incl, 31);
            }
            if (lane == 0) total_s[w] = carry;
        }
    }
    __syncthreads();

    // base (strictly-greater counts) + equal-score merge mask
    if (tid < VV) {
        const float sv = sc[tid];
        int b = 0; unsigned m = 0;
        #pragma unroll
        for (int u = 0; u < VV; u++) {
            if (sc[u] >  sv) b += total_s[u];
            if (sc[u] == sv) m |= (1u << u);
        }
        base_s[tid] = b;
        eqm[tid] = m;
    }
    __syncthreads();

    // ---- Pass C: compute ranks, scatter top_idx, count selected per class ----
    {
        int P[VV];
        #pragma unroll
        for (int u = 0; u < VV; u++) P[u] = pref[u][tid];
        int rc[VV] = {0, 0, 0, 0, 0, 0};
        int ls[VV] = {0, 0, 0, 0, 0, 0};

        #pragma unroll
        for (int l = 0; l < 16; l++) {
            const int v = tok[l];
            const unsigned m = eqm[v];
            int r = base_s[v];
            #pragma unroll
            for (int u = 0; u < VV; u++)
                if ((m >> u) & 1u) r += P[u] + rc[u];
            #pragma unroll
            for (int u = 0; u < VV; u++) rc[u] += (v == u);
            if (r < KK) {
                top_out[(size_t)row * KK + r] = (float)(tid * 16 + l);
                #pragma unroll
                for (int u = 0; u < VV; u++) ls[u] += (v == u);
            }
        }
        #pragma unroll
        for (int u = 0; u < VV; u++)
            if (ls[u]) atomicAdd(&selcnt[u], ls[u]);
    }
    __syncthreads();

    // ---- Pooling: pooled = sum_v selcnt[v]*att[v] / k ----
    if (tid < DD) {
        float s = 0.f;
        #pragma unroll
        for (int v = 0; v < VV; v++)
            s = fmaf((float)selcnt[v], att_s[v * DD + tid], s);
        pooled[tid] = s / (float)KK;
    }
    __syncthreads();

    // ---- Classifier ----
    if (tid < 64) {
        float s0 = 0.f, s1 = 0.f;
        #pragma unroll
        for (int d = 0; d < DD; d += 2) {
            s0 = fmaf(pooled[d + 0], C1[(d + 0) * 64 + tid], s0);
            s1 = fmaf(pooled[d + 1], C1[(d + 1) * 64 + tid], s1);
        }
        hbuf[tid] = fmaxf(s0 + s1 + c1[tid], 0.0f);
    }
    __syncthreads();

    if (tid == 0) {
        float s = c2[0];
        #pragma unroll
        for (int j = 0; j < 64; j++) s = fmaf(hbuf[j], C2[j], s);
        pred_out[row] = 1.0f / (1.0f + expf(-s));
    }
}

// ---------------------------------------------------------------------------
// Launch
// ---------------------------------------------------------------------------
extern "C" void kernel_launch(void* const* d_in, const int* in_sizes, int n_in,
                              void* d_out, int out_size) {
    const int*   x   = (const int*)  d_in[0];
    const float* emb = (const float*)d_in[1];
    const float* W1  = (const float*)d_in[2];
    const float* b1  = (const float*)d_in[3];
    const float* W2  = (const float*)d_in[4];
    const float* b2  = (const float*)d_in[5];
    const float* W3  = (const float*)d_in[6];
    const float* b3  = (const float*)d_in[7];
    const float* A1  = (const float*)d_in[8];
    const float* a1  = (const float*)d_in[9];
    const float* A2  = (const float*)d_in[10];
    const float* a2  = (const float*)d_in[11];
    const float* C1  = (const float*)d_in[12];
    const float* c1  = (const float*)d_in[13];
    const float* C2  = (const float*)d_in[14];
    const float* c2  = (const float*)d_in[15];
    float* out = (float*)d_out;

    k_tables<<<VV, DD>>>(emb, W1, b1, W2, b2, W3, b3, A1, a1, A2, a2);
    k_main<<<BB, 256>>>(x, C1, c1, C2, c2, out);
}